// round 15
// baseline (speedup 1.0000x reference)
#include <cuda_runtime.h>
#include <math.h>

constexpr int NN   = 512;
constexpr int JJ   = 20000;
constexpr int DIMM = JJ - 1;
constexpr int PP   = 8;
constexpr int JT   = 256;
constexpr int JB   = (JJ + JT - 1) / JT;   // 79
constexpr int RB   = 16;
constexpr int ROWS = NN / RB;              // 32 rows per block
constexpr int NPAIR = ROWS / 2;            // 16 row pairs
constexpr int W    = JB * 8;               // 632 warp columns
constexpr int LFMAX = 2048;
constexpr int GRID = JB * RB;              // 1264

constexpr float LOG2E = 1.4426950408889634f;
constexpr float LN2   = 0.6931471805599453f;

// Scratch (device globals)
__device__ float    g_rc[JJ * 2];       // (r, c-r); c = r*ln r - lnGamma(r) + 0.5*ln(2pi)
__device__ float    g_lf[LFMAX];        // -lnGamma(i+1) + 1/(12(i+1.44)) - i
__device__ unsigned g_pe[NN * W];       // per-(row,warp) sum exp(logit)*2^14 fixed point
__device__ unsigned g_py2[(NN/2) * W];  // per-(rowpair,warp) packed sum Y (lo|hi<<16)
__device__ float4   g_row[NN];          // {lse2, logs2, s, 0}
__device__ double   g_part[GRID];
__device__ unsigned g_done;             // last-block counter (self-resetting)

typedef unsigned long long ull;

__device__ __forceinline__ float lg2f(float x){ float r; asm("lg2.approx.f32 %0, %1;" : "=f"(r) : "f"(x)); return r; }
__device__ __forceinline__ float ex2f(float x){ float r; asm("ex2.approx.f32 %0, %1;" : "=f"(r) : "f"(x)); return r; }
__device__ __forceinline__ ull  pk2(float lo, float hi){ ull r; asm("mov.b64 %0, {%1,%2};" : "=l"(r) : "f"(lo), "f"(hi)); return r; }
__device__ __forceinline__ void upk2(ull v, float& lo, float& hi){ asm("mov.b64 {%0,%1}, %2;" : "=f"(lo), "=f"(hi) : "l"(v)); }
__device__ __forceinline__ ull fma2(ull a, ull b, ull c){ ull d; asm("fma.rn.f32x2 %0, %1, %2, %3;" : "=l"(d) : "l"(a), "l"(b), "l"(c)); return d; }
__device__ __forceinline__ ull add2(ull a, ull b){ ull d; asm("add.rn.f32x2 %0, %1, %2;" : "=l"(d) : "l"(a), "l"(b)); return d; }
__device__ __forceinline__ ull mul2(ull a, ull b){ ull d; asm("mul.rn.f32x2 %0, %1, %2;" : "=l"(d) : "l"(a), "l"(b)); return d; }
__device__ __forceinline__ unsigned redux_add(unsigned v){ unsigned r; asm("redux.sync.add.u32 %0, %1, 0xffffffff;" : "=r"(r) : "r"(v)); return r; }

// ---------------------------------------------------------------------------
// Kernel 1: row stats, f32x2 row-pair math. 3 redux per PAIR of elements.
// Per-gene precompute fused into the blockIdx.y==0 wave (consumed only by K3).
// ---------------------------------------------------------------------------
__global__ void __launch_bounds__(JT) k_rowpart(const float* __restrict__ mu,
                                                const float* __restrict__ beta,
                                                const float* __restrict__ phi,
                                                const float* __restrict__ X,
                                                const float* __restrict__ Y) {
    const int tid = threadIdx.x;
    const int j   = blockIdx.x * JT + tid;
    const bool valid = (j < JJ);
    const bool hasb  = (j < DIMM);

    // ---- fused one-time per-gene precompute (precise math) ----
    if (blockIdx.y == 0) {
        if (valid) {
            float ph = phi[j];
            float sp = fmaxf(ph, 0.0f) + log1pf(expf(-fabsf(ph)));   // softplus
            float r  = 1.0f / sp;
            float c  = fmaf(r, -logf(sp), -lgammaf(r)) + 0.9189385332046727f;
            g_rc[2 * j]     = r;
            g_rc[2 * j + 1] = c - r;     // fold -r so k_main skips the z term
        }
        if (j < LFMAX) {
            float fj = (float)j;
            g_lf[j] = -lgammaf(fj + 1.0f) + 1.0f / (12.0f * (fj + 1.44f)) - fj;
        }
    }

    // mu,beta pre-scaled by log2(e); +14 folds the 2^14 fixed-point scale
    float mu2 = 14.0f;
    ull b2[PP];
#pragma unroll
    for (int p = 0; p < PP; p++) b2[p] = 0ull;
    if (hasb) {
        mu2 = fmaf(mu[j], LOG2E, 14.0f);
#pragma unroll
        for (int p = 0; p < PP; p++) {
            float v = beta[(size_t)p * DIMM + j] * LOG2E;
            b2[p] = pk2(v, v);
        }
    }

    const int n0 = blockIdx.y * ROWS;
    __shared__ ulonglong2 s_x2[NPAIR * 4];   // X packed: row-pair x covariate-pair
    if (tid < NPAIR * 4) {
        int q = tid >> 2, pp = tid & 3;
        const float* xa = X + (size_t)(n0 + 2 * q) * PP + 2 * pp;
        const float* xb = xa + PP;
        s_x2[tid] = make_ulonglong2(pk2(xa[0], xb[0]), pk2(xa[1], xb[1]));
    }
    __syncthreads();

    const int lane = tid & 31, wid = tid >> 5;
    const int col  = blockIdx.x * 8 + wid;
    const ull mu2b = pk2(mu2, mu2);
    const float* yp = Y + (size_t)n0 * JJ + (valid ? j : 0);

#pragma unroll 4
    for (int q = 0; q < NPAIR; q++) {
        ulonglong2 x0 = s_x2[q * 4 + 0], x1 = s_x2[q * 4 + 1];
        ulonglong2 x2 = s_x2[q * 4 + 2], x3 = s_x2[q * 4 + 3];
        ull xb2 = mu2b;
        xb2 = fma2(x0.x, b2[0], xb2); xb2 = fma2(x0.y, b2[1], xb2);
        xb2 = fma2(x1.x, b2[2], xb2); xb2 = fma2(x1.y, b2[3], xb2);
        xb2 = fma2(x2.x, b2[4], xb2); xb2 = fma2(x2.y, b2[5], xb2);
        xb2 = fma2(x3.x, b2[6], xb2); xb2 = fma2(x3.y, b2[7], xb2);
        float t0, t1; upk2(xb2, t0, t1);
        float e0 = ex2f(t0), e1 = ex2f(t1);       // exp(logit) * 2^14
        float y0 = yp[0], y1 = yp[JJ]; yp += 2 * JJ;
        unsigned ei0 = valid ? __float2uint_rn(e0) : 0u;
        unsigned ei1 = valid ? __float2uint_rn(e1) : 0u;
        // pack the two rows' counts: per-warp sums < 2^16 each, no carry bleed
        unsigned yi = valid ? (__float2uint_rn(y0) + (__float2uint_rn(y1) << 16)) : 0u;
        unsigned es0 = redux_add(ei0);
        unsigned es1 = redux_add(ei1);
        unsigned ysp = redux_add(yi);
        if (lane == 0) {
            int n = n0 + 2 * q;
            g_pe[(size_t)n * W + col]       = es0;
            g_pe[(size_t)(n + 1) * W + col] = es1;
            g_py2[(size_t)(n >> 1) * W + col] = ysp;
        }
    }
}

// ---------------------------------------------------------------------------
// Kernel 2: finalize row stats, one block per row PAIR (exact integer sums).
// ---------------------------------------------------------------------------
__global__ void k_rowfinal() {
    const int n2 = blockIdx.x, tid = threadIdx.x;   // 128 threads, 256 blocks
    double e0 = 0.0, e1 = 0.0;
    unsigned yl = 0, yh = 0;
    for (int c = tid; c < W; c += 128) {
        e0 += (double)g_pe[(size_t)(2 * n2) * W + c];
        e1 += (double)g_pe[(size_t)(2 * n2 + 1) * W + c];
        unsigned v = g_py2[(size_t)n2 * W + c];
        yl += v & 0xffffu;
        yh += v >> 16;
    }
    const int lane = tid & 31, wid = tid >> 5;
    __shared__ double se0[4], se1[4];
    __shared__ unsigned sy0[4], sy1[4];
#pragma unroll
    for (int off = 16; off > 0; off >>= 1) {
        e0 += __shfl_down_sync(0xffffffffu, e0, off);
        e1 += __shfl_down_sync(0xffffffffu, e1, off);
        yl += __shfl_down_sync(0xffffffffu, yl, off);
        yh += __shfl_down_sync(0xffffffffu, yh, off);
    }
    if (lane == 0) { se0[wid] = e0; se1[wid] = e1; sy0[wid] = yl; sy1[wid] = yh; }
    __syncthreads();
    if (tid == 0) {
        double et0 = se0[0] + se0[1] + se0[2] + se0[3];
        double et1 = se1[0] + se1[1] + se1[2] + se1[3];
        float s0 = (float)(sy0[0] + sy0[1] + sy0[2] + sy0[3]);
        float s1 = (float)(sy1[0] + sy1[1] + sy1[2] + sy1[3]);
        g_row[2 * n2]     = make_float4((float)(log2(et0) - 14.0), log2f(s0), s0, 0.0f);
        g_row[2 * n2 + 1] = make_float4((float)(log2(et1) - 14.0), log2f(s1), s1, 0.0f);
    }
}

// ---------------------------------------------------------------------------
// Kernel 3: main NB loglik, f32x2 packed, fused final reduce.
// term = ln2*[(z-0.5)lg2 z - z*lg2(r+m) + y*(logs2+t2)] + (c-r) + slf[y]
//   where slf[y] = -lnGamma(y+1) + 1/(12(y+1.44)) - y   (all table-folded)
// ---------------------------------------------------------------------------
__global__ void __launch_bounds__(JT, 4) k_main(const float* __restrict__ mu,
                                                const float* __restrict__ beta,
                                                const float* __restrict__ Y,
                                                const float* __restrict__ X,
                                                float* __restrict__ out) {
    const int tid = threadIdx.x;
    const int j   = blockIdx.x * JT + tid;
    const bool valid = (j < JJ);
    const bool hasb  = (j < DIMM);

    float r = 1.0f, cj = 0.0f;
    if (valid) {
        float2 rc = ((const float2*)g_rc)[j];
        r = rc.x; cj = rc.y;             // cj = c - r
    }
    float mu2 = 0.0f;
    ull b2[PP];
#pragma unroll
    for (int p = 0; p < PP; p++) b2[p] = 0ull;
    if (hasb) {
        mu2 = mu[j] * LOG2E;
#pragma unroll
        for (int p = 0; p < PP; p++) {
            float v = beta[(size_t)p * DIMM + j] * LOG2E;
            b2[p] = pk2(v, v);
        }
    }

    const int n0 = blockIdx.y * ROWS;
    __shared__ ulonglong2 s_x2[NPAIR * 4];   // X packed: row-pair x covariate-pair
    __shared__ ulonglong2 s_ng[NPAIR];       // {(-lse2 pair), (logs2 pair)}
    __shared__ ull        s_s2[NPAIR];       // s pair
    __shared__ float      slf[LFMAX];        // folded log-factorial table (8 KB)
    if (tid < NPAIR * 4) {
        int q = tid >> 2, pp = tid & 3;
        const float* xa = X + (size_t)(n0 + 2 * q) * PP + 2 * pp;
        const float* xb = xa + PP;
        s_x2[tid] = make_ulonglong2(pk2(xa[0], xb[0]), pk2(xa[1], xb[1]));
    }
    if (tid < NPAIR) {
        float4 ra = g_row[n0 + 2 * tid], rb = g_row[n0 + 2 * tid + 1];
        s_ng[tid] = make_ulonglong2(pk2(-ra.x, -rb.x), pk2(ra.y, rb.y));
        s_s2[tid] = pk2(ra.z, rb.z);
    }
    for (int i = tid; i < LFMAX; i += JT) slf[i] = g_lf[i];
    __syncthreads();

    const ull mu2b = pk2(mu2, mu2);
    const ull r2b  = pk2(r, r);
    const ull cjb  = pk2(cj, cj);
    const ull cm1  = pk2(-1.0f, -1.0f);
    const ull cmh  = pk2(-0.5f, -0.5f);
    const ull ln2b = pk2(LN2, LN2);

    const float* yp = Y + (size_t)n0 * JJ + (valid ? j : 0);
    ull acc2 = 0ull;

#pragma unroll 2
    for (int q = 0; q < NPAIR; q++) {
        ulonglong2 x0 = s_x2[q * 4 + 0], x1 = s_x2[q * 4 + 1];
        ulonglong2 x2 = s_x2[q * 4 + 2], x3 = s_x2[q * 4 + 3];
        ull xb2 = mu2b;
        xb2 = fma2(x0.x, b2[0], xb2); xb2 = fma2(x0.y, b2[1], xb2);
        xb2 = fma2(x1.x, b2[2], xb2); xb2 = fma2(x1.y, b2[3], xb2);
        xb2 = fma2(x2.x, b2[4], xb2); xb2 = fma2(x2.y, b2[5], xb2);
        xb2 = fma2(x3.x, b2[6], xb2); xb2 = fma2(x3.y, b2[7], xb2);

        ulonglong2 ng = s_ng[q];
        ull t2 = add2(xb2, ng.x);                 // log2(pi)
        float t0, t1; upk2(t2, t0, t1);
        float e0 = ex2f(t0), e1 = ex2f(t1);       // pi
        ull rm2 = fma2(s_s2[q], pk2(e0, e1), r2b); // r + mean
        float rm0, rm1; upk2(rm2, rm0, rm1);
        ull lr = pk2(lg2f(rm0), lg2f(rm1));

        float y0 = yp[0], y1 = yp[JJ]; yp += 2 * JJ;
        ull y2 = pk2(y0, y1);
        ull z2 = add2(y2, r2b);
        float z0, z1; upk2(z2, z0, z1);
        ull lz = pk2(lg2f(z0), lg2f(z1));
        ull lf = pk2(slf[(int)y0], slf[(int)y1]);

        ull d  = fma2(lr, cm1, lz);               // lg2 z - lg2 rm
        ull G  = mul2(z2, d);
        G = fma2(lz, cmh, G);                     // -0.5*lg2 z
        ull lt2 = add2(ng.y, t2);                 // log2(mean)
        G = fma2(y2, lt2, G);
        ull H = add2(cjb, lf);                    // (c-r) + folded table
        acc2 = add2(acc2, fma2(ln2b, G, H));
    }

    float a0, a1; upk2(acc2, a0, a1);
    double d = valid ? (double)a0 + (double)a1 : 0.0;

    const int lane = tid & 31, wid = tid >> 5;
    __shared__ double sd[8];
#pragma unroll
    for (int off = 16; off > 0; off >>= 1)
        d += __shfl_down_sync(0xffffffffu, d, off);
    if (lane == 0) sd[wid] = d;
    __syncthreads();
    if (wid == 0) {
        double v = (lane < 8) ? sd[lane] : 0.0;
#pragma unroll
        for (int off = 4; off > 0; off >>= 1)
            v += __shfl_down_sync(0xffffffffu, v, off);
        if (lane == 0) g_part[blockIdx.y * JB + blockIdx.x] = v;
    }

    // ---- fused final reduction: last block to finish sums all partials ----
    __shared__ bool s_last;
    __threadfence();
    if (tid == 0) s_last = (atomicAdd(&g_done, 1u) == GRID - 1);
    __syncthreads();
    if (s_last) {
        double a = 0.0;
        for (int i = tid; i < GRID; i += JT) a += g_part[i];
#pragma unroll
        for (int off = 16; off > 0; off >>= 1)
            a += __shfl_down_sync(0xffffffffu, a, off);
        if (lane == 0) sd[wid] = a;
        __syncthreads();
        if (wid == 0) {
            double v = (lane < 8) ? sd[lane] : 0.0;
#pragma unroll
            for (int off = 4; off > 0; off >>= 1)
                v += __shfl_down_sync(0xffffffffu, v, off);
            if (lane == 0) { out[0] = (float)v; g_done = 0u; }
        }
    }
}

// ---------------------------------------------------------------------------
extern "C" void kernel_launch(void* const* d_in, const int* in_sizes, int n_in,
                              void* d_out, int out_size) {
    const float* mu   = (const float*)d_in[0];
    const float* beta = (const float*)d_in[1];
    const float* phi  = (const float*)d_in[2];
    const float* X    = (const float*)d_in[3];
    const float* Y    = (const float*)d_in[4];
    float* out = (float*)d_out;

    k_rowpart<<<dim3(JB, RB), JT>>>(mu, beta, phi, X, Y);
    k_rowfinal<<<NN / 2, 128>>>();
    k_main<<<dim3(JB, RB), JT>>>(mu, beta, Y, X, out);
}

// round 16
// speedup vs baseline: 1.0384x; 1.0384x over previous
#include <cuda_runtime.h>
#include <math.h>

constexpr int NN   = 512;
constexpr int JJ   = 20000;
constexpr int DIMM = JJ - 1;
constexpr int PP   = 8;
constexpr int JT   = 256;
constexpr int JB   = (JJ + JT - 1) / JT;   // 79
constexpr int RB   = 16;
constexpr int ROWS = NN / RB;              // 32 rows per block
constexpr int NPAIR = ROWS / 2;            // 16 row pairs
constexpr int W    = JB * 8;               // 632 warp columns
constexpr int LFMAX = 2048;
constexpr int GRID = JB * RB;              // 1264

constexpr float LOG2E = 1.4426950408889634f;
constexpr float LN2   = 0.6931471805599453f;

// Scratch (device globals)
__device__ float    g_rc[JJ * 2];       // (r, c-r); c = r*ln r - lnGamma(r) + 0.5*ln(2pi)
__device__ float    g_lf[LFMAX];        // -lnGamma(i+1) + 1/(12(i+1.44)) - i
__device__ unsigned g_pe[NN * W];       // per-(row,warp) sum exp(logit)*2^14 fixed point
__device__ unsigned g_py2[(NN/2) * W];  // per-(rowpair,warp) packed sum Y (lo|hi<<16)
__device__ float4   g_row[NN];          // {lse2, logs2, s, 0}
__device__ double   g_part[GRID];
__device__ unsigned g_done;             // last-block counter (self-resetting)

typedef unsigned long long ull;

__device__ __forceinline__ float lg2f(float x){ float r; asm("lg2.approx.f32 %0, %1;" : "=f"(r) : "f"(x)); return r; }
__device__ __forceinline__ float ex2f(float x){ float r; asm("ex2.approx.f32 %0, %1;" : "=f"(r) : "f"(x)); return r; }
__device__ __forceinline__ ull  pk2(float lo, float hi){ ull r; asm("mov.b64 %0, {%1,%2};" : "=l"(r) : "f"(lo), "f"(hi)); return r; }
__device__ __forceinline__ void upk2(ull v, float& lo, float& hi){ asm("mov.b64 {%0,%1}, %2;" : "=f"(lo), "=f"(hi) : "l"(v)); }
__device__ __forceinline__ ull fma2(ull a, ull b, ull c){ ull d; asm("fma.rn.f32x2 %0, %1, %2, %3;" : "=l"(d) : "l"(a), "l"(b), "l"(c)); return d; }
__device__ __forceinline__ ull add2(ull a, ull b){ ull d; asm("add.rn.f32x2 %0, %1, %2;" : "=l"(d) : "l"(a), "l"(b)); return d; }
__device__ __forceinline__ ull mul2(ull a, ull b){ ull d; asm("mul.rn.f32x2 %0, %1, %2;" : "=l"(d) : "l"(a), "l"(b)); return d; }
__device__ __forceinline__ unsigned redux_add(unsigned v){ unsigned r; asm("redux.sync.add.u32 %0, %1, 0xffffffff;" : "=r"(r) : "r"(v)); return r; }

// Split 8-fma2 dot product into two independent 4-chains (halves RAW latency).
__device__ __forceinline__ ull dot8(const ulonglong2* x, const ull* b, ull init) {
    ulonglong2 x0 = x[0], x1 = x[1], x2 = x[2], x3 = x[3];
    ull a = fma2(x0.x, b[0], init);
    ull c = mul2(x0.y, b[1]);
    a = fma2(x1.x, b[2], a);
    c = fma2(x1.y, b[3], c);
    a = fma2(x2.x, b[4], a);
    c = fma2(x2.y, b[5], c);
    a = fma2(x3.x, b[6], a);
    c = fma2(x3.y, b[7], c);
    return add2(a, c);
}

// ---------------------------------------------------------------------------
// Kernel 1: row stats, f32x2 row-pair math, 3 redux per pair, next-pair Y
// loads hoisted above the redux ops. Per-gene precompute fused into y==0 wave.
// ---------------------------------------------------------------------------
__global__ void __launch_bounds__(JT) k_rowpart(const float* __restrict__ mu,
                                                const float* __restrict__ beta,
                                                const float* __restrict__ phi,
                                                const float* __restrict__ X,
                                                const float* __restrict__ Y) {
    const int tid = threadIdx.x;
    const int j   = blockIdx.x * JT + tid;
    const bool valid = (j < JJ);
    const bool hasb  = (j < DIMM);

    // ---- fused one-time per-gene precompute (precise math) ----
    if (blockIdx.y == 0) {
        if (valid) {
            float ph = phi[j];
            float sp = fmaxf(ph, 0.0f) + log1pf(expf(-fabsf(ph)));   // softplus
            float r  = 1.0f / sp;
            float c  = fmaf(r, -logf(sp), -lgammaf(r)) + 0.9189385332046727f;
            g_rc[2 * j]     = r;
            g_rc[2 * j + 1] = c - r;
        }
        if (j < LFMAX) {
            float fj = (float)j;
            g_lf[j] = -lgammaf(fj + 1.0f) + 1.0f / (12.0f * (fj + 1.44f)) - fj;
        }
    }

    // mu,beta pre-scaled by log2(e); +14 folds the 2^14 fixed-point scale
    float mu2 = 14.0f;
    ull b2[PP];
#pragma unroll
    for (int p = 0; p < PP; p++) b2[p] = 0ull;
    if (hasb) {
        mu2 = fmaf(mu[j], LOG2E, 14.0f);
#pragma unroll
        for (int p = 0; p < PP; p++) {
            float v = beta[(size_t)p * DIMM + j] * LOG2E;
            b2[p] = pk2(v, v);
        }
    }

    const int n0 = blockIdx.y * ROWS;
    __shared__ ulonglong2 s_x2[NPAIR * 4];   // X packed: row-pair x covariate-pair
    if (tid < NPAIR * 4) {
        int q = tid >> 2, pp = tid & 3;
        const float* xa = X + (size_t)(n0 + 2 * q) * PP + 2 * pp;
        const float* xb = xa + PP;
        s_x2[tid] = make_ulonglong2(pk2(xa[0], xb[0]), pk2(xa[1], xb[1]));
    }
    __syncthreads();

    const int lane = tid & 31, wid = tid >> 5;
    const int col  = blockIdx.x * 8 + wid;
    const ull mu2b = pk2(mu2, mu2);
    const float* yp = Y + (size_t)n0 * JJ + (valid ? j : 0);

    // prefetch first pair's Y
    float y0 = yp[0], y1 = yp[JJ];

#pragma unroll
    for (int q = 0; q < NPAIR; q++) {
        ull xb2 = dot8(&s_x2[q * 4], b2, mu2b);
        float t0, t1; upk2(xb2, t0, t1);
        float e0 = ex2f(t0), e1 = ex2f(t1);       // exp(logit) * 2^14
        unsigned ei0 = valid ? __float2uint_rn(e0) : 0u;
        unsigned ei1 = valid ? __float2uint_rn(e1) : 0u;
        unsigned yi  = valid ? (__float2uint_rn(y0) + (__float2uint_rn(y1) << 16)) : 0u;
        // hoist next pair's Y loads above the redux chain
        if (q + 1 < NPAIR) { y0 = yp[2 * JJ]; y1 = yp[3 * JJ]; yp += 2 * JJ; }
        unsigned es0 = redux_add(ei0);
        unsigned es1 = redux_add(ei1);
        unsigned ysp = redux_add(yi);
        if (lane == 0) {
            int n = n0 + 2 * q;
            g_pe[(size_t)n * W + col]       = es0;
            g_pe[(size_t)(n + 1) * W + col] = es1;
            g_py2[(size_t)(n >> 1) * W + col] = ysp;
        }
    }
}

// ---------------------------------------------------------------------------
// Kernel 2: finalize row stats, one block per row PAIR (exact integer sums).
// ---------------------------------------------------------------------------
__global__ void k_rowfinal() {
    const int n2 = blockIdx.x, tid = threadIdx.x;   // 128 threads, 256 blocks
    double e0 = 0.0, e1 = 0.0;
    unsigned yl = 0, yh = 0;
    for (int c = tid; c < W; c += 128) {
        e0 += (double)g_pe[(size_t)(2 * n2) * W + c];
        e1 += (double)g_pe[(size_t)(2 * n2 + 1) * W + c];
        unsigned v = g_py2[(size_t)n2 * W + c];
        yl += v & 0xffffu;
        yh += v >> 16;
    }
    const int lane = tid & 31, wid = tid >> 5;
    __shared__ double se0[4], se1[4];
    __shared__ unsigned sy0[4], sy1[4];
#pragma unroll
    for (int off = 16; off > 0; off >>= 1) {
        e0 += __shfl_down_sync(0xffffffffu, e0, off);
        e1 += __shfl_down_sync(0xffffffffu, e1, off);
        yl += __shfl_down_sync(0xffffffffu, yl, off);
        yh += __shfl_down_sync(0xffffffffu, yh, off);
    }
    if (lane == 0) { se0[wid] = e0; se1[wid] = e1; sy0[wid] = yl; sy1[wid] = yh; }
    __syncthreads();
    if (tid == 0) {
        double et0 = se0[0] + se0[1] + se0[2] + se0[3];
        double et1 = se1[0] + se1[1] + se1[2] + se1[3];
        float s0 = (float)(sy0[0] + sy0[1] + sy0[2] + sy0[3]);
        float s1 = (float)(sy1[0] + sy1[1] + sy1[2] + sy1[3]);
        g_row[2 * n2]     = make_float4((float)(log2(et0) - 14.0), log2f(s0), s0, 0.0f);
        g_row[2 * n2 + 1] = make_float4((float)(log2(et1) - 14.0), log2f(s1), s1, 0.0f);
    }
}

// ---------------------------------------------------------------------------
// Kernel 3: main NB loglik, f32x2 packed, fused final reduce.
// term = ln2*[(z-0.5)lg2 z - z*lg2(r+m) + y*(logs2+t2)] + (c-r) + slf[y]
//   where slf[y] = -lnGamma(y+1) + 1/(12(y+1.44)) - y   (all table-folded)
// ---------------------------------------------------------------------------
__global__ void __launch_bounds__(JT, 5) k_main(const float* __restrict__ mu,
                                                const float* __restrict__ beta,
                                                const float* __restrict__ Y,
                                                const float* __restrict__ X,
                                                float* __restrict__ out) {
    const int tid = threadIdx.x;
    const int j   = blockIdx.x * JT + tid;
    const bool valid = (j < JJ);
    const bool hasb  = (j < DIMM);

    float r = 1.0f, cj = 0.0f;
    if (valid) {
        float2 rc = ((const float2*)g_rc)[j];
        r = rc.x; cj = rc.y;             // cj = c - r
    }
    float mu2 = 0.0f;
    ull b2[PP];
#pragma unroll
    for (int p = 0; p < PP; p++) b2[p] = 0ull;
    if (hasb) {
        mu2 = mu[j] * LOG2E;
#pragma unroll
        for (int p = 0; p < PP; p++) {
            float v = beta[(size_t)p * DIMM + j] * LOG2E;
            b2[p] = pk2(v, v);
        }
    }

    const int n0 = blockIdx.y * ROWS;
    __shared__ ulonglong2 s_x2[NPAIR * 4];   // X packed: row-pair x covariate-pair
    __shared__ ulonglong2 s_ng[NPAIR];       // {(-lse2 pair), (logs2 pair)}
    __shared__ ull        s_s2[NPAIR];       // s pair
    __shared__ float      slf[LFMAX];        // folded log-factorial table (8 KB)
    if (tid < NPAIR * 4) {
        int q = tid >> 2, pp = tid & 3;
        const float* xa = X + (size_t)(n0 + 2 * q) * PP + 2 * pp;
        const float* xb = xa + PP;
        s_x2[tid] = make_ulonglong2(pk2(xa[0], xb[0]), pk2(xa[1], xb[1]));
    }
    if (tid < NPAIR) {
        float4 ra = g_row[n0 + 2 * tid], rb = g_row[n0 + 2 * tid + 1];
        s_ng[tid] = make_ulonglong2(pk2(-ra.x, -rb.x), pk2(ra.y, rb.y));
        s_s2[tid] = pk2(ra.z, rb.z);
    }
    for (int i = tid; i < LFMAX; i += JT) slf[i] = g_lf[i];
    __syncthreads();

    const ull mu2b = pk2(mu2, mu2);
    const ull r2b  = pk2(r, r);
    const ull cjb  = pk2(cj, cj);
    const ull cm1  = pk2(-1.0f, -1.0f);
    const ull cmh  = pk2(-0.5f, -0.5f);
    const ull ln2b = pk2(LN2, LN2);

    const float* yp = Y + (size_t)n0 * JJ + (valid ? j : 0);
    ull acc2 = 0ull;

#pragma unroll 2
    for (int q = 0; q < NPAIR; q++) {
        ull xb2 = dot8(&s_x2[q * 4], b2, mu2b);

        ulonglong2 ng = s_ng[q];
        ull t2 = add2(xb2, ng.x);                 // log2(pi)
        float t0, t1; upk2(t2, t0, t1);
        float e0 = ex2f(t0), e1 = ex2f(t1);       // pi
        ull rm2 = fma2(s_s2[q], pk2(e0, e1), r2b); // r + mean
        float rm0, rm1; upk2(rm2, rm0, rm1);
        ull lr = pk2(lg2f(rm0), lg2f(rm1));

        float y0 = yp[0], y1 = yp[JJ]; yp += 2 * JJ;
        ull y2 = pk2(y0, y1);
        ull z2 = add2(y2, r2b);
        float z0, z1; upk2(z2, z0, z1);
        ull lz = pk2(lg2f(z0), lg2f(z1));
        ull lf = pk2(slf[(int)y0], slf[(int)y1]);

        ull d  = fma2(lr, cm1, lz);               // lg2 z - lg2 rm
        ull G  = mul2(z2, d);
        G = fma2(lz, cmh, G);                     // -0.5*lg2 z
        ull lt2 = add2(ng.y, t2);                 // log2(mean)
        G = fma2(y2, lt2, G);
        ull H = add2(cjb, lf);                    // (c-r) + folded table
        acc2 = add2(acc2, fma2(ln2b, G, H));
    }

    float a0, a1; upk2(acc2, a0, a1);
    double d = valid ? (double)a0 + (double)a1 : 0.0;

    const int lane = tid & 31, wid = tid >> 5;
    __shared__ double sd[8];
#pragma unroll
    for (int off = 16; off > 0; off >>= 1)
        d += __shfl_down_sync(0xffffffffu, d, off);
    if (lane == 0) sd[wid] = d;
    __syncthreads();
    if (wid == 0) {
        double v = (lane < 8) ? sd[lane] : 0.0;
#pragma unroll
        for (int off = 4; off > 0; off >>= 1)
            v += __shfl_down_sync(0xffffffffu, v, off);
        if (lane == 0) g_part[blockIdx.y * JB + blockIdx.x] = v;
    }

    // ---- fused final reduction: last block to finish sums all partials ----
    __shared__ bool s_last;
    __threadfence();
    if (tid == 0) s_last = (atomicAdd(&g_done, 1u) == GRID - 1);
    __syncthreads();
    if (s_last) {
        double a = 0.0;
        for (int i = tid; i < GRID; i += JT) a += g_part[i];
#pragma unroll
        for (int off = 16; off > 0; off >>= 1)
            a += __shfl_down_sync(0xffffffffu, a, off);
        if (lane == 0) sd[wid] = a;
        __syncthreads();
        if (wid == 0) {
            double v = (lane < 8) ? sd[lane] : 0.0;
#pragma unroll
            for (int off = 4; off > 0; off >>= 1)
                v += __shfl_down_sync(0xffffffffu, v, off);
            if (lane == 0) { out[0] = (float)v; g_done = 0u; }
        }
    }
}

// ---------------------------------------------------------------------------
extern "C" void kernel_launch(void* const* d_in, const int* in_sizes, int n_in,
                              void* d_out, int out_size) {
    const float* mu   = (const float*)d_in[0];
    const float* beta = (const float*)d_in[1];
    const float* phi  = (const float*)d_in[2];
    const float* X    = (const float*)d_in[3];
    const float* Y    = (const float*)d_in[4];
    float* out = (float*)d_out;

    k_rowpart<<<dim3(JB, RB), JT>>>(mu, beta, phi, X, Y);
    k_rowfinal<<<NN / 2, 128>>>();
    k_main<<<dim3(JB, RB), JT>>>(mu, beta, Y, X, out);
}